// round 15
// baseline (speedup 1.0000x reference)
#include <cuda_runtime.h>

#define TSTEPS  1024
#define BATCH   64
#define IN_DIM  256
#define HID_DIM 512
#define OUT_DIM 256
#define KDIM    768
#define NCTA    128
#define NTHR    512

// strides in floats
#define HSTRIDE_B (1025 * HID_DIM)
#define RSTRIDE_B (1025 * OUT_DIM)
#define XSTRIDE_B (TSTEPS * IN_DIM)

// smem: W1s[32][768] + W2s[16][768] + biases
#define W1_ROWS 32
#define W2_ROWS 16
#define SMEM_FLOATS (W1_ROWS * KDIM + W2_ROWS * KDIM + W1_ROWS + W2_ROWS)

// ---- global-barrier state (init + final reset only) ----
__device__ unsigned g_bar_count = 0;
__device__ volatile unsigned g_bar_gen = 0;

// ---- per-batch-group monotonic epoch counters (separate 256B L2 sectors) ----
// 256 warp-arrivals per epoch per batch-group (16 CTAs x 16 warps)
__device__ unsigned g_cnt[8 * 64];

__device__ __forceinline__ void grid_barrier() {
    __syncthreads();
    if (threadIdx.x == 0) {
        __threadfence();
        unsigned g = g_bar_gen;
        if (atomicAdd(&g_bar_count, 1u) == NCTA - 1) {
            g_bar_count = 0;
            __threadfence();
            g_bar_gen = g + 1;
        } else {
            while (g_bar_gen == g) {}
            __threadfence();
        }
    }
    __syncthreads();
}

__device__ __forceinline__ void red_release_add1(unsigned* p) {
    asm volatile("red.release.gpu.add.u32 [%0], 1;" :: "l"(p) : "memory");
}
__device__ __forceinline__ unsigned ld_acquire_u32(const unsigned* p) {
    unsigned v;
    asm volatile("ld.acquire.gpu.u32 %0, [%1];" : "=r"(v) : "l"(p) : "memory");
    return v;
}

// Persistent RNN kernel, v12 = v9 body + hybrid sync:
//   arrival:  per-warp (__syncwarp + lane0 red.release.gpu)  -> no __syncthreads
//   detect:   single poller (tid 0) + volatile smem flag relay -> 1 reader/counter/CTA
// 128 CTAs = 8 batch-groups x 16 col-groups. CTA = 512 threads = 16 warps.
//   col-group cg owns h-cols [cg*32,+32), r-cols [cg*16,+16); bg owns 8 rows.
//   warp = (col-part cp 0..7: 4 h-cols + 2 r-cols) x (row-half rh: 4 rows)
//   lane = k-slice (k = 4*lane + 128*i); 576 FFMA/thr/iter.
__global__ void __launch_bounds__(NTHR, 1)
rnn_persistent_kernel(const float* __restrict__ X,    // [64][1024][256]
                      const float* __restrict__ H0,   // [64][512]
                      const float* __restrict__ R0,   // [64][256]
                      const float* __restrict__ Wih,  // [512][768]
                      const float* __restrict__ Bih,  // [512]
                      const float* __restrict__ Who,  // [256][768]
                      const float* __restrict__ Bho,  // [256]
                      float* __restrict__ Rout,       // [64][1025][256]
                      float* __restrict__ Hout)       // [64][1025][512]
{
    extern __shared__ float smem[];
    float* W1s   = smem;                     // [32][768]
    float* W2s   = smem + W1_ROWS * KDIM;    // [16][768]
    float* bih_s = W2s + W2_ROWS * KDIM;     // [32]
    float* bho_s = bih_s + W1_ROWS;          // [16]
    volatile __shared__ int bar_flag;

    const int tid  = threadIdx.x;
    const int cta  = blockIdx.x;
    const int bg   = cta & 7;         // batch group (8 rows)
    const int cg   = cta >> 3;        // col group (32 h + 16 r cols)
    const int b0   = bg * 8;
    const int jh0  = cg * 32;
    const int jr0  = cg * 16;
    const int wrp  = tid >> 5;
    const int lane = tid & 31;
    const int cp   = wrp >> 1;        // col part: 4 h-cols + 2 r-cols
    const int rh   = wrp & 1;         // row half
    const int bb0  = b0 + rh * 4;
    unsigned* cnt  = &g_cnt[bg * 64];

    // ---- stationary weight slices -> smem (coalesced over k) ----
    for (int idx = tid; idx < W1_ROWS * KDIM; idx += NTHR) {
        int j = idx / KDIM, k = idx - j * KDIM;
        W1s[idx] = Wih[(jh0 + j) * KDIM + k];
    }
    for (int idx = tid; idx < W2_ROWS * KDIM; idx += NTHR) {
        int j = idx / KDIM, k = idx - j * KDIM;
        W2s[idx] = Who[(jr0 + j) * KDIM + k];
    }
    if (tid < W1_ROWS) bih_s[tid] = Bih[jh0 + tid];
    if (tid < W2_ROWS) bho_s[tid] = Bho[jr0 + tid];
    if (tid == 0) bar_flag = 0;

    // ---- t=0 states into output/exchange buffers ----
    for (int idx = tid; idx < 8 * 32; idx += NTHR) {
        int b = b0 + (idx >> 5), jj = idx & 31;
        Hout[(size_t)b * HSTRIDE_B + jh0 + jj] = H0[b * HID_DIM + jh0 + jj];
    }
    for (int idx = tid; idx < 8 * 16; idx += NTHR) {
        int b = b0 + (idx >> 4), jj = idx & 15;
        Rout[(size_t)b * RSTRIDE_B + jr0 + jj] = R0[b * OUT_DIM + jr0 + jj];
    }
    __syncthreads();   // weights + flag + states ready

    // ---- per-warp smem weight bases ----
    const float* W1p = &W1s[(cp * 4) * KDIM];   // 4 h-col rows
    const float* W2p = &W2s[(cp * 2) * KDIM];   // 2 r-col rows

    // ---- running pointers ----
    const float* pHr = Hout + (size_t)bb0 * HSTRIDE_B + 4 * lane;           // h[t=0]
    const float* pX  = X    + (size_t)bb0 * XSTRIDE_B + 4 * lane;           // x[t=0]
    const float* pRr = Rout + (size_t)bb0 * RSTRIDE_B + 4 * lane - OUT_DIM; // r[t=-1] (guarded)

    // per-lane store pointer + bias: lane<24, flat out idx = lane
    const int bl = lane / 6, oc = lane % 6;
    float* pW = 0; float bias = 0.f; int wstep = 0;
    if (lane < 24) {
        if (oc < 4) {   // h output: slot t=1, stores h[it+1]
            pW    = Hout + (size_t)(bb0 + bl) * HSTRIDE_B + HID_DIM + jh0 + cp * 4 + oc;
            bias  = bih_s[cp * 4 + oc];
            wstep = HID_DIM;
        } else {        // r output: slot t=0, stores r[it] (guarded it>=1)
            pW    = Rout + (size_t)(bb0 + bl) * RSTRIDE_B + jr0 + cp * 2 + (oc - 4);
            bias  = bho_s[cp * 2 + (oc - 4)];
            wstep = OUT_DIM;
        }
    }

    // A[b*6+c]: c 0..3 h-cols, c 4..5 r-cols
    float A[24];
#pragma unroll
    for (int i = 0; i < 24; ++i) A[i] = 0.f;

    // ---- prologue: x-dot for it=0 ----
#pragma unroll
    for (int i = 0; i < 2; ++i) {
        float4 w[4];
#pragma unroll
        for (int c = 0; c < 4; ++c) w[c] = *(const float4*)&W1p[c * KDIM + 4 * lane + 128 * i];
#pragma unroll
        for (int b = 0; b < 4; ++b) {
            const float4 a = *(const float4*)&pX[b * XSTRIDE_B + 128 * i];
#pragma unroll
            for (int c = 0; c < 4; ++c)
                A[b * 6 + c] += a.x * w[c].x + a.y * w[c].y
                              + a.z * w[c].z + a.w * w[c].w;
        }
    }
    pX += IN_DIM;

    grid_barrier();  // one-time: all t=0 states visible chip-wide

    for (int it = 0; it <= TSTEPS; ++it) {
        // ---- h[it] feeds h-dot (W_ih k=256..767) and r-dot (W_ho k=0..511) ----
#pragma unroll
        for (int i = 0; i < 4; ++i) {
            float4 w1[4], w2[2];
#pragma unroll
            for (int c = 0; c < 4; ++c) w1[c] = *(const float4*)&W1p[c * KDIM + 256 + 4 * lane + 128 * i];
#pragma unroll
            for (int c = 0; c < 2; ++c) w2[c] = *(const float4*)&W2p[c * KDIM + 4 * lane + 128 * i];
#pragma unroll
            for (int b = 0; b < 4; ++b) {
                const float4 a = *(const float4*)&pHr[b * HSTRIDE_B + 128 * i];
#pragma unroll
                for (int c = 0; c < 4; ++c)
                    A[b * 6 + c] += a.x * w1[c].x + a.y * w1[c].y
                                  + a.z * w1[c].z + a.w * w1[c].w;
#pragma unroll
                for (int c = 0; c < 2; ++c)
                    A[b * 6 + 4 + c] += a.x * w2[c].x + a.y * w2[c].y
                                      + a.z * w2[c].z + a.w * w2[c].w;
            }
        }

        // ---- r[it-1] contribution (W_ho k = 512..767) ----
        if (it >= 1) {
#pragma unroll
            for (int i = 0; i < 2; ++i) {
                float4 w2[2];
#pragma unroll
                for (int c = 0; c < 2; ++c) w2[c] = *(const float4*)&W2p[c * KDIM + 512 + 4 * lane + 128 * i];
#pragma unroll
                for (int b = 0; b < 4; ++b) {
                    const float4 a = *(const float4*)&pRr[b * RSTRIDE_B + 128 * i];
#pragma unroll
                    for (int c = 0; c < 2; ++c)
                        A[b * 6 + 4 + c] += a.x * w2[c].x + a.y * w2[c].y
                                          + a.z * w2[c].z + a.w * w2[c].w;
                }
            }
        }

        // ---- transpose-butterfly reduction: 31 shuffles, output L lands on lane L ----
#pragma unroll
        for (int off = 16; off >= 1; off >>= 1) {
#pragma unroll
            for (int i = 0; i < off && i < 24; ++i) {
                const int j = i + off;
                const float vj = (j < 24) ? A[j] : 0.f;
                const float send = (lane & off) ? A[i] : vj;
                const float recv = __shfl_xor_sync(0xffffffffu, send, off);
                const float keep = (lane & off) ? vj : A[i];
                A[i] = keep + recv;
            }
        }

        // ---- bias + relu + store ----
        if (lane < 24) {
            const float v = fmaxf(A[0] + bias, 0.f);
            if (oc < 4) {
                if (it < TSTEPS) *pW = v;   // h[it+1]
            } else {
                if (it >= 1) *pW = v;       // r[it]
            }
        }

        if (it == TSTEPS) break;

        // ---- per-warp arrival: this warp's stores are complete ----
        __syncwarp();                            // order lane stores within warp
        if (lane == 0) red_release_add1(cnt);    // release THIS warp's stores

        // ---- post-arrival window: zero accs, fold x-dot for it+1, advance ----
#pragma unroll
        for (int i = 0; i < 24; ++i) A[i] = 0.f;
        if (it + 1 < TSTEPS) {
#pragma unroll
            for (int i = 0; i < 2; ++i) {
                float4 w[4];
#pragma unroll
                for (int c = 0; c < 4; ++c) w[c] = *(const float4*)&W1p[c * KDIM + 4 * lane + 128 * i];
#pragma unroll
                for (int b = 0; b < 4; ++b) {
                    const float4 a = *(const float4*)&pX[b * XSTRIDE_B + 128 * i];
#pragma unroll
                    for (int c = 0; c < 4; ++c)
                        A[b * 6 + c] += a.x * w[c].x + a.y * w[c].y
                                      + a.z * w[c].z + a.w * w[c].w;
                }
            }
        }
        pX  += IN_DIM;
        pHr += HID_DIM;
        pRr += OUT_DIM;
        if (lane < 24) pW += wstep;

        // ---- wait: all 256 warps of this bg signaled epoch it+1 ----
        // single poller per CTA (16 readers/counter total), smem flag relay
        const int epoch = it + 1;
        if (tid == 0) {
            const unsigned tgt = 256u * (unsigned)epoch;
            while ((int)(ld_acquire_u32(cnt) - tgt) < 0) {}
            bar_flag = epoch;
        } else if (lane == 0) {
            while (bar_flag < epoch) {}
        }
        __syncwarp();
    }

    // ---- reset epoch counters for the next graph replay ----
    grid_barrier();
    if (cta < 8 && tid == 0) g_cnt[cta * 64] = 0;
}

extern "C" void kernel_launch(void* const* d_in, const int* in_sizes, int n_in,
                              void* d_out, int out_size) {
    const float* X   = (const float*)d_in[0];
    const float* H0  = (const float*)d_in[1];
    const float* R0  = (const float*)d_in[2];
    const float* Wih = (const float*)d_in[3];
    const float* Bih = (const float*)d_in[4];
    const float* Who = (const float*)d_in[5];
    const float* Bho = (const float*)d_in[6];

    float* Rout = (float*)d_out;                                   // [64][1025][256]
    float* Hout = (float*)d_out + (size_t)BATCH * 1025 * OUT_DIM;  // [64][1025][512]

    static int smem_set = 0;
    const int smem_bytes = SMEM_FLOATS * (int)sizeof(float);
    if (!smem_set) {
        cudaFuncSetAttribute(rnn_persistent_kernel,
                             cudaFuncAttributeMaxDynamicSharedMemorySize, smem_bytes);
        smem_set = 1;
    }
    rnn_persistent_kernel<<<NCTA, NTHR, smem_bytes>>>(X, H0, R0, Wih, Bih, Who, Bho,
                                                      Rout, Hout);
}

// round 16
// speedup vs baseline: 2.0605x; 2.0605x over previous
#include <cuda_runtime.h>

#define TSTEPS  1024
#define BATCH   64
#define IN_DIM  256
#define HID_DIM 512
#define OUT_DIM 256
#define KDIM    768
#define NCTA    128
#define NTHR    512

// strides in floats
#define HSTRIDE_B (1025 * HID_DIM)
#define RSTRIDE_B (1025 * OUT_DIM)
#define XSTRIDE_B (TSTEPS * IN_DIM)

// smem: W1s[32][768] + W2s[16][768] + biases
#define W1_ROWS 32
#define W2_ROWS 16
#define SMEM_FLOATS (W1_ROWS * KDIM + W2_ROWS * KDIM + W1_ROWS + W2_ROWS)

// ---- global-barrier state (init + final reset only) ----
__device__ unsigned g_bar_count = 0;
__device__ volatile unsigned g_bar_gen = 0;

// ---- monotonic epoch counters: hcnt = g_cnt[bg*64], rcnt = g_cnt[512+bg*64] ----
// 16 CTA-arrivals per epoch per batch-group per counter
__device__ unsigned g_cnt[16 * 64];

__device__ __forceinline__ void grid_barrier() {
    __syncthreads();
    if (threadIdx.x == 0) {
        __threadfence();
        unsigned g = g_bar_gen;
        if (atomicAdd(&g_bar_count, 1u) == NCTA - 1) {
            g_bar_count = 0;
            __threadfence();
            g_bar_gen = g + 1;
        } else {
            while (g_bar_gen == g) {}
            __threadfence();
        }
    }
    __syncthreads();
}

__device__ __forceinline__ void red_release_add1(unsigned* p) {
    asm volatile("red.release.gpu.add.u32 [%0], 1;" :: "l"(p) : "memory");
}
__device__ __forceinline__ unsigned ld_acquire_u32(const unsigned* p) {
    unsigned v;
    asm volatile("ld.acquire.gpu.u32 %0, [%1];" : "=r"(v) : "l"(p) : "memory");
    return v;
}

// Persistent RNN kernel, v13 = v9 partition + EARLY h-SIGNAL phase split,
// with spin-toxicity-safe waits (the v10 post-mortem fix):
//   wait#1 (h[it], the real dependency): v9-style single poller + smem flag —
//           safe because no concurrent compute exists in that window.
//   wait#2 (r[it-1], one full iteration of slack -> normally pre-satisfied):
//           per-warp direct L2 ld.acquire with __nanosleep backoff — the
//           benign spin class (~3 instr / 250 cyc), cannot starve computers.
// Per iteration:
//   wait#1 -> h-dot (single h load feeds w1->HA, w2->RA) -> HA-reduce ->
//   store h[it+1] -> __syncthreads -> SIGNAL hcnt            <- critical chain
//   x-prefold x[it+1] -> wait#2 -> r-dot (w2r·r[it-1]->RA) -> RA-reduce ->
//   store r[it] -> __syncthreads -> SIGNAL rcnt               <- overlap window
// 128 CTAs = 8 batch-groups x 16 col-groups, 512 thr, v9 lane/col mapping.
__global__ void __launch_bounds__(NTHR, 1)
rnn_persistent_kernel(const float* __restrict__ X,    // [64][1024][256]
                      const float* __restrict__ H0,   // [64][512]
                      const float* __restrict__ R0,   // [64][256]
                      const float* __restrict__ Wih,  // [512][768]
                      const float* __restrict__ Bih,  // [512]
                      const float* __restrict__ Who,  // [256][768]
                      const float* __restrict__ Bho,  // [256]
                      float* __restrict__ Rout,       // [64][1025][256]
                      float* __restrict__ Hout)       // [64][1025][512]
{
    extern __shared__ float smem[];
    float* W1s   = smem;                     // [32][768]
    float* W2s   = smem + W1_ROWS * KDIM;    // [16][768]
    float* bih_s = W2s + W2_ROWS * KDIM;     // [32]
    float* bho_s = bih_s + W1_ROWS;          // [16]
    volatile __shared__ int bar_flag;

    const int tid  = threadIdx.x;
    const int cta  = blockIdx.x;
    const int bg   = cta & 7;         // batch group (8 rows)
    const int cg   = cta >> 3;        // col group (32 h + 16 r cols)
    const int b0   = bg * 8;
    const int jh0  = cg * 32;
    const int jr0  = cg * 16;
    const int wrp  = tid >> 5;
    const int lane = tid & 31;
    const int cp   = wrp >> 1;        // col part: 4 h-cols + 2 r-cols
    const int rh   = wrp & 1;         // row half
    const int bb0  = b0 + rh * 4;
    unsigned* hcnt = &g_cnt[bg * 64];
    unsigned* rcnt = &g_cnt[512 + bg * 64];

    // ---- stationary weight slices -> smem (coalesced over k) ----
    for (int idx = tid; idx < W1_ROWS * KDIM; idx += NTHR) {
        int j = idx / KDIM, k = idx - j * KDIM;
        W1s[idx] = Wih[(jh0 + j) * KDIM + k];
    }
    for (int idx = tid; idx < W2_ROWS * KDIM; idx += NTHR) {
        int j = idx / KDIM, k = idx - j * KDIM;
        W2s[idx] = Who[(jr0 + j) * KDIM + k];
    }
    if (tid < W1_ROWS) bih_s[tid] = Bih[jh0 + tid];
    if (tid < W2_ROWS) bho_s[tid] = Bho[jr0 + tid];
    if (tid == 0) bar_flag = 0;

    // ---- t=0 states into output/exchange buffers ----
    for (int idx = tid; idx < 8 * 32; idx += NTHR) {
        int b = b0 + (idx >> 5), jj = idx & 31;
        Hout[(size_t)b * HSTRIDE_B + jh0 + jj] = H0[b * HID_DIM + jh0 + jj];
    }
    for (int idx = tid; idx < 8 * 16; idx += NTHR) {
        int b = b0 + (idx >> 4), jj = idx & 15;
        Rout[(size_t)b * RSTRIDE_B + jr0 + jj] = R0[b * OUT_DIM + jr0 + jj];
    }
    __syncthreads();   // weights + flag + states ready

    // ---- per-warp smem weight bases ----
    const float* W1p = &W1s[(cp * 4) * KDIM];   // 4 h-col rows
    const float* W2p = &W2s[(cp * 2) * KDIM];   // 2 r-col rows

    // ---- running pointers ----
    const float* pHr = Hout + (size_t)bb0 * HSTRIDE_B + 4 * lane;           // h[t=0]
    const float* pX  = X    + (size_t)bb0 * XSTRIDE_B + 4 * lane;           // x[t=0]
    const float* pRr = Rout + (size_t)bb0 * RSTRIDE_B + 4 * lane - OUT_DIM; // r[t=-1] (guarded)

    // h store: lane<16 -> (row lane>>2, col lane&3); slot t=1, advances
    float* pWh = Hout + (size_t)(bb0 + (lane >> 2)) * HSTRIDE_B + HID_DIM
               + jh0 + cp * 4 + (lane & 3);
    const float bias_h = bih_s[cp * 4 + (lane & 3)];
    // r store: lane<8 -> (row lane>>1, col lane&1); slot t=0, advances (store guarded it>=1)
    float* pWr = Rout + (size_t)(bb0 + (lane >> 1)) * RSTRIDE_B
               + jr0 + cp * 2 + (lane & 1);
    const float bias_r = bho_s[cp * 2 + (lane & 1)];

    float HA[16];   // h accumulators HA[b*4+c]
    float RA[8];    // r accumulators RA[b*2+c]
#pragma unroll
    for (int i = 0; i < 16; ++i) HA[i] = 0.f;
#pragma unroll
    for (int i = 0; i < 8; ++i) RA[i] = 0.f;

    // ---- prologue: x-dot for it=0 ----
#pragma unroll
    for (int i = 0; i < 2; ++i) {
        float4 w[4];
#pragma unroll
        for (int c = 0; c < 4; ++c) w[c] = *(const float4*)&W1p[c * KDIM + 4 * lane + 128 * i];
#pragma unroll
        for (int b = 0; b < 4; ++b) {
            const float4 a = *(const float4*)&pX[b * XSTRIDE_B + 128 * i];
#pragma unroll
            for (int c = 0; c < 4; ++c)
                HA[b * 4 + c] += a.x * w[c].x + a.y * w[c].y
                               + a.z * w[c].z + a.w * w[c].w;
        }
    }
    pX += IN_DIM;

    grid_barrier();  // one-time: all t=0 states visible chip-wide

    for (int it = 0; it <= TSTEPS; ++it) {
        // ===== wait#1: h[it] visible (hcnt >= 16*it) — v9-style relay =====
        if (it > 0) {
            if (tid == 0) {
                const unsigned tgt = 16u * (unsigned)it;
                while ((int)(ld_acquire_u32(hcnt) - tgt) < 0) {}
                bar_flag = it;
            } else if (lane == 0) {
                while (bar_flag < it) {}
            }
            __syncwarp();
        }

        // ===== h-phase: single h[it] load feeds w1->HA and w2->RA =====
#pragma unroll
        for (int i = 0; i < 4; ++i) {
            float4 w1[4], w2[2];
#pragma unroll
            for (int c = 0; c < 4; ++c) w1[c] = *(const float4*)&W1p[c * KDIM + 256 + 4 * lane + 128 * i];
#pragma unroll
            for (int c = 0; c < 2; ++c) w2[c] = *(const float4*)&W2p[c * KDIM + 4 * lane + 128 * i];
#pragma unroll
            for (int b = 0; b < 4; ++b) {
                const float4 a = *(const float4*)&pHr[b * HSTRIDE_B + 128 * i];
#pragma unroll
                for (int c = 0; c < 4; ++c)
                    HA[b * 4 + c] += a.x * w1[c].x + a.y * w1[c].y
                                   + a.z * w1[c].z + a.w * w1[c].w;
#pragma unroll
                for (int c = 0; c < 2; ++c)
                    RA[b * 2 + c] += a.x * w2[c].x + a.y * w2[c].y
                                   + a.z * w2[c].z + a.w * w2[c].w;
            }
        }

        // HA-reduce: butterfly over 16, lane L<16 gets output L
#pragma unroll
        for (int off = 16; off >= 1; off >>= 1) {
#pragma unroll
            for (int i = 0; i < off && i < 16; ++i) {
                const int j = i + off;
                const float vj = (j < 16) ? HA[j] : 0.f;
                const float send = (lane & off) ? HA[i] : vj;
                const float recv = __shfl_xor_sync(0xffffffffu, send, off);
                const float keep = (lane & off) ? vj : HA[i];
                HA[i] = keep + recv;
            }
        }
        if (it < TSTEPS && lane < 16) *pWh = fmaxf(HA[0] + bias_h, 0.f);  // h[it+1]

        __syncthreads();                        // all h stores issued CTA-wide
        if (tid == 0) red_release_add1(hcnt);   // SIGNAL#1: h[it+1] visible

        // ===== overlap window: x-prefold x[it+1] into HA =====
#pragma unroll
        for (int i = 0; i < 16; ++i) HA[i] = 0.f;
        if (it + 1 < TSTEPS) {
#pragma unroll
            for (int i = 0; i < 2; ++i) {
                float4 w[4];
#pragma unroll
                for (int c = 0; c < 4; ++c) w[c] = *(const float4*)&W1p[c * KDIM + 4 * lane + 128 * i];
#pragma unroll
                for (int b = 0; b < 4; ++b) {
                    const float4 a = *(const float4*)&pX[b * XSTRIDE_B + 128 * i];
#pragma unroll
                    for (int c = 0; c < 4; ++c)
                        HA[b * 4 + c] += a.x * w[c].x + a.y * w[c].y
                                       + a.z * w[c].z + a.w * w[c].w;
                }
            }
        }

        // ===== wait#2: r[it-1] visible (rcnt >= 16*(it-1) cadence -> target 16*(it-1))
        // one full iteration of slack: normally pre-satisfied. Per-warp direct
        // L2 ld.acquire + nanosleep backoff (benign spin class).
        if (it >= 2) {
            if (lane == 0) {
                const unsigned tgt = 16u * (unsigned)(it - 1);
                while ((int)(ld_acquire_u32(rcnt) - tgt) < 0) __nanosleep(32);
            }
            __syncwarp();
        }

        // ===== r-phase: RA += w2r·r[it-1]; reduce; store r[it] =====
        if (it >= 1) {
#pragma unroll
            for (int i = 0; i < 2; ++i) {
                float4 w2[2];
#pragma unroll
                for (int c = 0; c < 2; ++c) w2[c] = *(const float4*)&W2p[c * KDIM + 512 + 4 * lane + 128 * i];
#pragma unroll
                for (int b = 0; b < 4; ++b) {
                    const float4 a = *(const float4*)&pRr[b * RSTRIDE_B + 128 * i];
#pragma unroll
                    for (int c = 0; c < 2; ++c)
                        RA[b * 2 + c] += a.x * w2[c].x + a.y * w2[c].y
                                       + a.z * w2[c].z + a.w * w2[c].w;
                }
            }

            // RA-reduce: butterfly over 8, lane L<8 gets output L
#pragma unroll
            for (int off = 16; off >= 1; off >>= 1) {
#pragma unroll
                for (int i = 0; i < off && i < 8; ++i) {
                    const int j = i + off;
                    const float vj = (j < 8) ? RA[j] : 0.f;
                    const float send = (lane & off) ? RA[i] : vj;
                    const float recv = __shfl_xor_sync(0xffffffffu, send, off);
                    const float keep = (lane & off) ? vj : RA[i];
                    RA[i] = keep + recv;
                }
            }
            if (lane < 8) *pWr = fmaxf(RA[0] + bias_r, 0.f);   // r[it]
        }

        if (it == TSTEPS) break;

        __syncthreads();                        // all r stores issued CTA-wide
        if (tid == 0) red_release_add1(rcnt);   // SIGNAL#2: r[it] visible

        // ===== advance =====
#pragma unroll
        for (int i = 0; i < 8; ++i) RA[i] = 0.f;
        pX  += IN_DIM;
        pHr += HID_DIM;
        pRr += OUT_DIM;
        pWh += HID_DIM;
        pWr += OUT_DIM;
    }

    // ---- reset epoch counters for the next graph replay ----
    grid_barrier();
    if (tid == 0) {
        if (cta < 8)       g_cnt[cta * 64] = 0;
        else if (cta < 16) g_cnt[512 + (cta - 8) * 64] = 0;
    }
}

extern "C" void kernel_launch(void* const* d_in, const int* in_sizes, int n_in,
                              void* d_out, int out_size) {
    const float* X   = (const float*)d_in[0];
    const float* H0  = (const float*)d_in[1];
    const float* R0  = (const float*)d_in[2];
    const float* Wih = (const float*)d_in[3];
    const float* Bih = (const float*)d_in[4];
    const float* Who = (const float*)d_in[5];
    const float* Bho = (const float*)d_in[6];

    float* Rout = (float*)d_out;                                   // [64][1025][256]
    float* Hout = (float*)d_out + (size_t)BATCH * 1025 * OUT_DIM;  // [64][1025][512]

    static int smem_set = 0;
    const int smem_bytes = SMEM_FLOATS * (int)sizeof(float);
    if (!smem_set) {
        cudaFuncSetAttribute(rnn_persistent_kernel,
                             cudaFuncAttributeMaxDynamicSharedMemorySize, smem_bytes);
        smem_set = 1;
    }
    rnn_persistent_kernel<<<NCTA, NTHR, smem_bytes>>>(X, H0, R0, Wih, Bih, Who, Bho,
                                                      Rout, Hout);
}

// round 17
// speedup vs baseline: 2.6931x; 1.3070x over previous
#include <cuda_runtime.h>

#define TSTEPS  1024
#define BATCH   64
#define IN_DIM  256
#define HID_DIM 512
#define OUT_DIM 256
#define KDIM    768
#define NCTA    128
#define NTHR    512

// strides in floats
#define HSTRIDE_B (1025 * HID_DIM)
#define RSTRIDE_B (1025 * OUT_DIM)
#define XSTRIDE_B (TSTEPS * IN_DIM)

// smem: W1s[32][768] + W2s[16][768] + biases
#define W1_ROWS 32
#define W2_ROWS 16
#define SMEM_FLOATS (W1_ROWS * KDIM + W2_ROWS * KDIM + W1_ROWS + W2_ROWS)

// ---- global-barrier state (init + final reset only) ----
__device__ unsigned g_bar_count = 0;
__device__ volatile unsigned g_bar_gen = 0;

// ---- per-batch-group monotonic epoch counters (separate 256B L2 sectors) ----
__device__ unsigned g_cnt[8 * 64];

__device__ __forceinline__ void grid_barrier() {
    __syncthreads();
    if (threadIdx.x == 0) {
        __threadfence();
        unsigned g = g_bar_gen;
        if (atomicAdd(&g_bar_count, 1u) == NCTA - 1) {
            g_bar_count = 0;
            __threadfence();
            g_bar_gen = g + 1;
        } else {
            while (g_bar_gen == g) {}
            __threadfence();
        }
    }
    __syncthreads();
}

__device__ __forceinline__ void red_release_add1(unsigned* p) {
    asm volatile("red.release.gpu.add.u32 [%0], 1;" :: "l"(p) : "memory");
}
__device__ __forceinline__ unsigned ld_acquire_u32(const unsigned* p) {
    unsigned v;
    asm volatile("ld.acquire.gpu.u32 %0, [%1];" : "=r"(v) : "l"(p) : "memory");
    return v;
}

// Persistent RNN kernel, v14 = v9 with the epoch wait converted to BAR-sleep.
// 128 CTAs = 8 batch-groups x 16 col-groups. CTA = 512 threads = 16 warps.
//   col-group cg owns h-cols [cg*32,+32), r-cols [cg*16,+16); bg owns 8 rows.
//   warp = (col-part cp 0..7: 4 h-cols + 2 r-cols) x (row-half rh: 4 rows)
//   lane = k-slice (k = 4*lane + 128*i); 576 FFMA/thr/iter.
// Sync per iteration:
//   __syncthreads (stores issued) -> tid0 red.release(cnt) -> x-prefold ->
//   tid0 ld.acquire-polls cnt >= 16*(it+1) (ONLY poller) ->
//   __syncthreads: all other warps SLEEP at the barrier (no issue pressure,
//   unlike v9's LDS flag spin which interfered with late warps' x-prefold).
__global__ void __launch_bounds__(NTHR, 1)
rnn_persistent_kernel(const float* __restrict__ X,    // [64][1024][256]
                      const float* __restrict__ H0,   // [64][512]
                      const float* __restrict__ R0,   // [64][256]
                      const float* __restrict__ Wih,  // [512][768]
                      const float* __restrict__ Bih,  // [512]
                      const float* __restrict__ Who,  // [256][768]
                      const float* __restrict__ Bho,  // [256]
                      float* __restrict__ Rout,       // [64][1025][256]
                      float* __restrict__ Hout)       // [64][1025][512]
{
    extern __shared__ float smem[];
    float* W1s   = smem;                     // [32][768]
    float* W2s   = smem + W1_ROWS * KDIM;    // [16][768]
    float* bih_s = W2s + W2_ROWS * KDIM;     // [32]
    float* bho_s = bih_s + W1_ROWS;          // [16]

    const int tid  = threadIdx.x;
    const int cta  = blockIdx.x;
    const int bg   = cta & 7;         // batch group (8 rows)
    const int cg   = cta >> 3;        // col group (32 h + 16 r cols)
    const int b0   = bg * 8;
    const int jh0  = cg * 32;
    const int jr0  = cg * 16;
    const int wrp  = tid >> 5;
    const int lane = tid & 31;
    const int cp   = wrp >> 1;        // col part: 4 h-cols + 2 r-cols
    const int rh   = wrp & 1;         // row half
    const int bb0  = b0 + rh * 4;
    unsigned* cnt  = &g_cnt[bg * 64];

    // ---- stationary weight slices -> smem (coalesced over k) ----
    for (int idx = tid; idx < W1_ROWS * KDIM; idx += NTHR) {
        int j = idx / KDIM, k = idx - j * KDIM;
        W1s[idx] = Wih[(jh0 + j) * KDIM + k];
    }
    for (int idx = tid; idx < W2_ROWS * KDIM; idx += NTHR) {
        int j = idx / KDIM, k = idx - j * KDIM;
        W2s[idx] = Who[(jr0 + j) * KDIM + k];
    }
    if (tid < W1_ROWS) bih_s[tid] = Bih[jh0 + tid];
    if (tid < W2_ROWS) bho_s[tid] = Bho[jr0 + tid];

    // ---- t=0 states into output/exchange buffers ----
    for (int idx = tid; idx < 8 * 32; idx += NTHR) {
        int b = b0 + (idx >> 5), jj = idx & 31;
        Hout[(size_t)b * HSTRIDE_B + jh0 + jj] = H0[b * HID_DIM + jh0 + jj];
    }
    for (int idx = tid; idx < 8 * 16; idx += NTHR) {
        int b = b0 + (idx >> 4), jj = idx & 15;
        Rout[(size_t)b * RSTRIDE_B + jr0 + jj] = R0[b * OUT_DIM + jr0 + jj];
    }
    __syncthreads();   // weights + states ready

    // ---- per-warp smem weight bases ----
    const float* W1p = &W1s[(cp * 4) * KDIM];   // 4 h-col rows
    const float* W2p = &W2s[(cp * 2) * KDIM];   // 2 r-col rows

    // ---- running pointers ----
    const float* pHr = Hout + (size_t)bb0 * HSTRIDE_B + 4 * lane;           // h[t=0]
    const float* pX  = X    + (size_t)bb0 * XSTRIDE_B + 4 * lane;           // x[t=0]
    const float* pRr = Rout + (size_t)bb0 * RSTRIDE_B + 4 * lane - OUT_DIM; // r[t=-1] (guarded)

    // per-lane store pointer + bias: lane<24, flat out idx = lane
    const int bl = lane / 6, oc = lane % 6;
    float* pW = 0; float bias = 0.f; int wstep = 0;
    if (lane < 24) {
        if (oc < 4) {   // h output: slot t=1, stores h[it+1]
            pW    = Hout + (size_t)(bb0 + bl) * HSTRIDE_B + HID_DIM + jh0 + cp * 4 + oc;
            bias  = bih_s[cp * 4 + oc];
            wstep = HID_DIM;
        } else {        // r output: slot t=0, stores r[it] (guarded it>=1)
            pW    = Rout + (size_t)(bb0 + bl) * RSTRIDE_B + jr0 + cp * 2 + (oc - 4);
            bias  = bho_s[cp * 2 + (oc - 4)];
            wstep = OUT_DIM;
        }
    }

    // A[b*6+c]: c 0..3 h-cols, c 4..5 r-cols
    float A[24];
#pragma unroll
    for (int i = 0; i < 24; ++i) A[i] = 0.f;

    // ---- prologue: x-dot for it=0 ----
#pragma unroll
    for (int i = 0; i < 2; ++i) {
        float4 w[4];
#pragma unroll
        for (int c = 0; c < 4; ++c) w[c] = *(const float4*)&W1p[c * KDIM + 4 * lane + 128 * i];
#pragma unroll
        for (int b = 0; b < 4; ++b) {
            const float4 a = *(const float4*)&pX[b * XSTRIDE_B + 128 * i];
#pragma unroll
            for (int c = 0; c < 4; ++c)
                A[b * 6 + c] += a.x * w[c].x + a.y * w[c].y
                              + a.z * w[c].z + a.w * w[c].w;
        }
    }
    pX += IN_DIM;

    grid_barrier();  // one-time: all t=0 states visible chip-wide

    for (int it = 0; it <= TSTEPS; ++it) {
        // ---- h[it] feeds h-dot (W_ih k=256..767) and r-dot (W_ho k=0..511) ----
#pragma unroll
        for (int i = 0; i < 4; ++i) {
            float4 w1[4], w2[2];
#pragma unroll
            for (int c = 0; c < 4; ++c) w1[c] = *(const float4*)&W1p[c * KDIM + 256 + 4 * lane + 128 * i];
#pragma unroll
            for (int c = 0; c < 2; ++c) w2[c] = *(const float4*)&W2p[c * KDIM + 4 * lane + 128 * i];
#pragma unroll
            for (int b = 0; b < 4; ++b) {
                const float4 a = *(const float4*)&pHr[b * HSTRIDE_B + 128 * i];
#pragma unroll
                for (int c = 0; c < 4; ++c)
                    A[b * 6 + c] += a.x * w1[c].x + a.y * w1[c].y
                                  + a.z * w1[c].z + a.w * w1[c].w;
#pragma unroll
                for (int c = 0; c < 2; ++c)
                    A[b * 6 + 4 + c] += a.x * w2[c].x + a.y * w2[c].y
                                      + a.z * w2[c].z + a.w * w2[c].w;
            }
        }

        // ---- r[it-1] contribution (W_ho k = 512..767) ----
        if (it >= 1) {
#pragma unroll
            for (int i = 0; i < 2; ++i) {
                float4 w2[2];
#pragma unroll
                for (int c = 0; c < 2; ++c) w2[c] = *(const float4*)&W2p[c * KDIM + 512 + 4 * lane + 128 * i];
#pragma unroll
                for (int b = 0; b < 4; ++b) {
                    const float4 a = *(const float4*)&pRr[b * RSTRIDE_B + 128 * i];
#pragma unroll
                    for (int c = 0; c < 2; ++c)
                        A[b * 6 + 4 + c] += a.x * w2[c].x + a.y * w2[c].y
                                          + a.z * w2[c].z + a.w * w2[c].w;
                }
            }
        }

        // ---- transpose-butterfly reduction: 31 shuffles, output L lands on lane L ----
#pragma unroll
        for (int off = 16; off >= 1; off >>= 1) {
#pragma unroll
            for (int i = 0; i < off && i < 24; ++i) {
                const int j = i + off;
                const float vj = (j < 24) ? A[j] : 0.f;
                const float send = (lane & off) ? A[i] : vj;
                const float recv = __shfl_xor_sync(0xffffffffu, send, off);
                const float keep = (lane & off) ? vj : A[i];
                A[i] = keep + recv;
            }
        }

        // ---- bias + relu + store ----
        if (lane < 24) {
            const float v = fmaxf(A[0] + bias, 0.f);
            if (oc < 4) {
                if (it < TSTEPS) *pW = v;   // h[it+1]
            } else {
                if (it >= 1) *pW = v;       // r[it]
            }
        }

        if (it == TSTEPS) break;

        __syncthreads();                       // all CTA stores issued
        if (tid == 0) red_release_add1(cnt);   // arrive (release)

        // ---- wait window: zero accs, fold x-dot for it+1, advance pointers ----
#pragma unroll
        for (int i = 0; i < 24; ++i) A[i] = 0.f;
        if (it + 1 < TSTEPS) {
#pragma unroll
            for (int i = 0; i < 2; ++i) {
                float4 w[4];
#pragma unroll
                for (int c = 0; c < 4; ++c) w[c] = *(const float4*)&W1p[c * KDIM + 4 * lane + 128 * i];
#pragma unroll
                for (int b = 0; b < 4; ++b) {
                    const float4 a = *(const float4*)&pX[b * XSTRIDE_B + 128 * i];
#pragma unroll
                    for (int c = 0; c < 4; ++c)
                        A[b * 6 + c] += a.x * w[c].x + a.y * w[c].y
                                      + a.z * w[c].z + a.w * w[c].w;
                }
            }
        }
        pX  += IN_DIM;
        pHr += HID_DIM;
        pRr += OUT_DIM;
        if (lane < 24) pW += wstep;

        // ---- wait for this batch-group's epoch (16 arrivals/iter) ----
        // tid0 is the ONLY poller (tight L2 loop, critical path); all other
        // warps SLEEP at the barrier — zero issue pressure during the wait.
        if (tid == 0) {
            const unsigned tgt = 16u * (unsigned)(it + 1);
            while ((int)(ld_acquire_u32(cnt) - tgt) < 0) {}
        }
        __syncthreads();   // BAR-sleep wait; released when tid0 arrives
    }

    // ---- reset epoch counters for the next graph replay ----
    grid_barrier();
    if (cta < 8 && tid == 0) g_cnt[cta * 64] = 0;
}

extern "C" void kernel_launch(void* const* d_in, const int* in_sizes, int n_in,
                              void* d_out, int out_size) {
    const float* X   = (const float*)d_in[0];
    const float* H0  = (const float*)d_in[1];
    const float* R0  = (const float*)d_in[2];
    const float* Wih = (const float*)d_in[3];
    const float* Bih = (const float*)d_in[4];
    const float* Who = (const float*)d_in[5];
    const float* Bho = (const float*)d_in[6];

    float* Rout = (float*)d_out;                                   // [64][1025][256]
    float* Hout = (float*)d_out + (size_t)BATCH * 1025 * OUT_DIM;  // [64][1025][512]

    static int smem_set = 0;
    const int smem_bytes = SMEM_FLOATS * (int)sizeof(float);
    if (!smem_set) {
        cudaFuncSetAttribute(rnn_persistent_kernel,
                             cudaFuncAttributeMaxDynamicSharedMemorySize, smem_bytes);
        smem_set = 1;
    }
    rnn_persistent_kernel<<<NCTA, NTHR, smem_bytes>>>(X, H0, R0, Wih, Bih, Who, Bho,
                                                      Rout, Hout);
}